// round 1
// baseline (speedup 1.0000x reference)
#include <cuda_runtime.h>
#include <math.h>

#define B_ 4
#define N_ 65536
#define K_ 16
#define D_ 8
#define OUT_ 8
#define EPS_ 1e-6f
#define SLOPE_ 0.2f

// 16 floats per point: [x,y,z,pad, f0..f7, pad x4] -> 64B record, sector aligned
__device__ float4 g_rec[(size_t)B_ * N_ * 4];
__device__ double g_sums[16];          // sum_y[0..7], sum_y2[8..15]
__device__ float  g_wp[64];            // [0..7]=W0, [8+o*3+i]=A, [32+o*3+i]=C, [56..63]=bias
__device__ float  g_scale[8];
__device__ float  g_shift[8];

// ---------------- Pass 0: pack records, zero stats, prep weights ----------------
__global__ void __launch_bounds__(256) k0_pack(const float* __restrict__ coords,
                                               const float* __restrict__ feats,
                                               const float* __restrict__ conv_w,
                                               const float* __restrict__ conv_b) {
    int t = blockIdx.x * blockDim.x + threadIdx.x;
    if (blockIdx.x == 0) {
        if (threadIdx.x < 16) g_sums[threadIdx.x] = 0.0;
        if (threadIdx.x < 8) {
            int o = threadIdx.x;
            const float* w = conv_w + o * 10;
            g_wp[o] = w[0];
            #pragma unroll
            for (int i = 0; i < 3; i++) {
                g_wp[8  + o * 3 + i] = w[1 + i] + w[4 + i];   // A: ext coeff
                g_wp[32 + o * 3 + i] = w[7 + i] - w[1 + i];   // C: nb coeff
            }
            g_wp[56 + o] = conv_b[o];
        }
    }
    if (t >= B_ * N_) return;
    int b = t >> 16;
    int n = t & (N_ - 1);
    float4 c4;
    c4.x = coords[(size_t)t * 3 + 0];
    c4.y = coords[(size_t)t * 3 + 1];
    c4.z = coords[(size_t)t * 3 + 2];
    c4.w = 0.f;
    const float* fb = feats + (size_t)b * D_ * N_ + n;
    float4 f0, f1;
    f0.x = fb[0 * N_]; f0.y = fb[1 * N_]; f0.z = fb[2 * N_]; f0.w = fb[3 * N_];
    f1.x = fb[4 * N_]; f1.y = fb[5 * N_]; f1.z = fb[6 * N_]; f1.w = fb[7 * N_];
    float4* r = &g_rec[(size_t)t * 4];
    r[0] = c4; r[1] = f0; r[2] = f1;
}

// ---------------- Pass 1: BN statistics (sum, sumsq per channel) ----------------
__global__ void __launch_bounds__(256) k1_stats(const int* __restrict__ idx) {
    int t = blockIdx.x * blockDim.x + threadIdx.x;   // one (b,n) per thread
    int b = t >> 16;
    int base = b << 16;
    const float4* rec = g_rec;
    float4 ext = rec[(size_t)t * 4];

    float e[8], W0[8], C[24];
    #pragma unroll
    for (int o = 0; o < 8; o++) {
        W0[o] = g_wp[o];
        e[o]  = g_wp[56 + o] + g_wp[8 + o * 3] * ext.x + g_wp[9 + o * 3] * ext.y
                             + g_wp[10 + o * 3] * ext.z;
        C[o * 3 + 0] = g_wp[32 + o * 3];
        C[o * 3 + 1] = g_wp[33 + o * 3];
        C[o * 3 + 2] = g_wp[34 + o * 3];
    }

    float sy[8], sy2[8];
    #pragma unroll
    for (int o = 0; o < 8; o++) { sy[o] = 0.f; sy2[o] = 0.f; }

    const int4* ip = (const int4*)idx + (size_t)t * 4;
    #pragma unroll
    for (int kk = 0; kk < 4; kk++) {
        int4 j4 = ip[kk];
        int js[4] = {j4.x, j4.y, j4.z, j4.w};
        #pragma unroll
        for (int u = 0; u < 4; u++) {
            float4 nb = rec[(size_t)(base + js[u]) * 4];
            float rx = ext.x - nb.x, ry = ext.y - nb.y, rz = ext.z - nb.z;
            float d = sqrtf(rx * rx + ry * ry + rz * rz);
            #pragma unroll
            for (int o = 0; o < 8; o++) {
                float y = e[o] + W0[o] * d + C[o*3] * nb.x + C[o*3+1] * nb.y + C[o*3+2] * nb.z;
                sy[o]  += y;
                sy2[o] += y * y;
            }
        }
    }

    // warp reduce
    #pragma unroll
    for (int o = 0; o < 8; o++) {
        #pragma unroll
        for (int off = 16; off > 0; off >>= 1) {
            sy[o]  += __shfl_down_sync(0xffffffffu, sy[o],  off);
            sy2[o] += __shfl_down_sync(0xffffffffu, sy2[o], off);
        }
    }
    __shared__ float ps[16];
    if (threadIdx.x < 16) ps[threadIdx.x] = 0.f;
    __syncthreads();
    if ((threadIdx.x & 31) == 0) {
        #pragma unroll
        for (int o = 0; o < 8; o++) {
            atomicAdd(&ps[o],     sy[o]);
            atomicAdd(&ps[8 + o], sy2[o]);
        }
    }
    __syncthreads();
    if (threadIdx.x < 16) atomicAdd(&g_sums[threadIdx.x], (double)ps[threadIdx.x]);
}

// ---------------- Pass 1.5: finalize BN scale/shift ----------------
__global__ void k2_final(const float* __restrict__ gamma, const float* __restrict__ beta) {
    int o = threadIdx.x;
    if (o < 8) {
        double M    = (double)B_ * N_ * K_;
        double mean = g_sums[o] / M;
        double var  = g_sums[8 + o] / M - mean * mean;
        float  sc   = (float)((double)gamma[o] / sqrt(var + (double)EPS_));
        g_scale[o]  = sc;
        g_shift[o]  = beta[o] - (float)mean * sc;
    }
}

// ---------------- Pass 2: recompute y, apply BN+LeakyReLU, write both outputs ----------------
__global__ void __launch_bounds__(256) k3_out(const int* __restrict__ idx,
                                              float* __restrict__ out) {
    int t  = blockIdx.x * blockDim.x + threadIdx.x;  // [0, B*N*4)
    int kg = t & 3;
    int pn = t >> 2;               // b*N + n
    int b  = pn >> 16;
    int n  = pn & (N_ - 1);
    int base = b << 16;

    const float4* rec = g_rec;
    float4 ext = rec[(size_t)pn * 4];

    float e[8], W0[8], C[24];
    #pragma unroll
    for (int o = 0; o < 8; o++) {
        W0[o] = g_wp[o];
        e[o]  = g_wp[56 + o] + g_wp[8 + o * 3] * ext.x + g_wp[9 + o * 3] * ext.y
                             + g_wp[10 + o * 3] * ext.z;
        C[o * 3 + 0] = g_wp[32 + o * 3];
        C[o * 3 + 1] = g_wp[33 + o * 3];
        C[o * 3 + 2] = g_wp[34 + o * 3];
    }

    int4 j4 = ((const int4*)idx)[(size_t)pn * 4 + kg];
    int js[4] = {j4.x, j4.y, j4.z, j4.w};

    float ybuf[4][8];
    float fbuf[4][8];
    #pragma unroll
    for (int u = 0; u < 4; u++) {
        size_t ro = (size_t)(base + js[u]) * 4;
        float4 nb = rec[ro];
        float4 f0 = rec[ro + 1];
        float4 f1 = rec[ro + 2];
        fbuf[u][0] = f0.x; fbuf[u][1] = f0.y; fbuf[u][2] = f0.z; fbuf[u][3] = f0.w;
        fbuf[u][4] = f1.x; fbuf[u][5] = f1.y; fbuf[u][6] = f1.z; fbuf[u][7] = f1.w;
        float rx = ext.x - nb.x, ry = ext.y - nb.y, rz = ext.z - nb.z;
        float d = sqrtf(rx * rx + ry * ry + rz * rz);
        #pragma unroll
        for (int o = 0; o < 8; o++) {
            ybuf[u][o] = e[o] + W0[o] * d + C[o*3] * nb.x + C[o*3+1] * nb.y + C[o*3+2] * nb.z;
        }
    }

    const size_t plane = (size_t)N_ * K_;                 // 1M elems per (b,c) plane
    const size_t pos   = (size_t)n * K_ + (size_t)kg * 4;
    float* o1 = out + (size_t)b * 16 * plane + pos;                       // (B,16,N,K)
    float* o2 = out + (size_t)B_ * 16 * plane + (size_t)b * 8 * plane + pos; // (B,8,N,K)

    // neighbour-feature channels 0..7
    #pragma unroll
    for (int d = 0; d < 8; d++) {
        float4 v = make_float4(fbuf[0][d], fbuf[1][d], fbuf[2][d], fbuf[3][d]);
        *(float4*)(o1 + (size_t)d * plane) = v;
    }
    // BN + LeakyReLU channels 8..15 (and second output)
    #pragma unroll
    for (int o = 0; o < 8; o++) {
        float sc = g_scale[o], sh = g_shift[o];
        float4 v;
        v.x = fmaf(ybuf[0][o], sc, sh);
        v.y = fmaf(ybuf[1][o], sc, sh);
        v.z = fmaf(ybuf[2][o], sc, sh);
        v.w = fmaf(ybuf[3][o], sc, sh);
        v.x = fmaxf(v.x, SLOPE_ * v.x);
        v.y = fmaxf(v.y, SLOPE_ * v.y);
        v.z = fmaxf(v.z, SLOPE_ * v.z);
        v.w = fmaxf(v.w, SLOPE_ * v.w);
        *(float4*)(o1 + (size_t)(8 + o) * plane) = v;
        *(float4*)(o2 + (size_t)o * plane)       = v;
    }
}

extern "C" void kernel_launch(void* const* d_in, const int* in_sizes, int n_in,
                              void* d_out, int out_size) {
    const float* coords = (const float*)d_in[0];
    const float* feats  = (const float*)d_in[1];
    const int*   idx    = (const int*)d_in[2];
    const float* conv_w = (const float*)d_in[3];
    const float* conv_b = (const float*)d_in[4];
    const float* gamma  = (const float*)d_in[5];
    const float* beta   = (const float*)d_in[6];
    float* out = (float*)d_out;

    k0_pack<<<(B_ * N_ + 255) / 256, 256>>>(coords, feats, conv_w, conv_b);
    k1_stats<<<(B_ * N_) / 256, 256>>>(idx);
    k2_final<<<1, 32>>>(gamma, beta);
    k3_out<<<(B_ * N_ * 4) / 256, 256>>>(idx, out);
}